// round 1
// baseline (speedup 1.0000x reference)
#include <cuda_runtime.h>

#define HH 264
#define WW 264
#define HWP (HH*WW)      // 69696
#define C 96
#define C3 288
#define SHIFT 4
#define QK_STRIDE 68     // padded token-stride for q/k smem rows

// ---- scratch (static device globals; allocation is forbidden) ----
__device__ float g_qkv[C3 * HWP];   // after 1x1 conv (shifted frame)
__device__ float g_dw [C3 * HWP];   // after depthwise 3x3
__device__ float g_pred[C * HWP];   // attention scatter-add accumulator

__constant__ int c_off[5] = {0, 50, 100, 150, 200};

// --------------------------------------------------------------------------
// K0: zero the accumulator
// --------------------------------------------------------------------------
__global__ void zero_pred_kernel() {
    int i = blockIdx.x * blockDim.x + threadIdx.x;
    if (i < C * HWP) g_pred[i] = 0.0f;
}

// --------------------------------------------------------------------------
// K1: qkv = qkv_w @ x_shifted   (M=288, K=96, N=69696)
// block computes 96 oc x 64 px, 256 threads, K fully staged in smem.
// The (-4,-4) roll is folded into the input gather.
// --------------------------------------------------------------------------
__global__ __launch_bounds__(256) void qkv_gemm_kernel(
    const float* __restrict__ x, const float* __restrict__ w)
{
    __shared__ float sW[96][97];
    __shared__ float sX[96][64];
    __shared__ int   s_src[64];

    const int tid = threadIdx.x;
    const int p0  = blockIdx.x * 64;
    const int oc0 = blockIdx.y * 96;

    if (tid < 64) {
        int p = p0 + tid;
        int h = p / WW, ww = p % WW;
        int hs = h + SHIFT; if (hs >= HH) hs -= HH;
        int ws = ww + SHIFT; if (ws >= WW) ws -= WW;
        s_src[tid] = hs * WW + ws;
    }
    for (int i = tid; i < 96 * 96; i += 256) {
        int r = i / 96, k = i % 96;
        sW[r][k] = w[(oc0 + r) * 96 + k];
    }
    __syncthreads();
    for (int i = tid; i < 96 * 64; i += 256) {
        int k = i >> 6, px = i & 63;
        sX[k][px] = x[k * HWP + s_src[px]];
    }
    __syncthreads();

    const int ty = tid >> 4, tx = tid & 15;
    float acc[6][4] = {};
    #pragma unroll 4
    for (int k = 0; k < 96; k++) {
        float a[6], b[4];
        #pragma unroll
        for (int i = 0; i < 6; i++) a[i] = sW[ty + 16 * i][k];
        #pragma unroll
        for (int j = 0; j < 4; j++) b[j] = sX[k][tx + 16 * j];
        #pragma unroll
        for (int i = 0; i < 6; i++)
            #pragma unroll
            for (int j = 0; j < 4; j++)
                acc[i][j] += a[i] * b[j];
    }
    #pragma unroll
    for (int i = 0; i < 6; i++)
        #pragma unroll
        for (int j = 0; j < 4; j++)
            g_qkv[(oc0 + ty + 16 * i) * HWP + p0 + tx + 16 * j] = acc[i][j];
}

// --------------------------------------------------------------------------
// K2: depthwise 3x3, pad 1, 288 channels (shifted frame)
// --------------------------------------------------------------------------
__global__ __launch_bounds__(256) void dwconv_kernel(const float* __restrict__ dww)
{
    const int c = blockIdx.y;
    const int p = blockIdx.x * 256 + threadIdx.x;
    if (p >= HWP) return;
    const int h = p / WW, w_ = p % WW;
    const float* in = g_qkv + c * HWP;
    const float* wt = dww + c * 9;

    float s = 0.0f;
    #pragma unroll
    for (int ky = 0; ky < 3; ky++) {
        int y = h + ky - 1;
        if ((unsigned)y >= HH) continue;
        #pragma unroll
        for (int kx = 0; kx < 3; kx++) {
            int xx = w_ + kx - 1;
            if ((unsigned)xx >= WW) continue;
            s += __ldg(&wt[ky * 3 + kx]) * __ldg(&in[y * WW + xx]);
        }
    }
    g_dw[c * HWP + p] = s;
}

// --------------------------------------------------------------------------
// K3: per-window channel attention. 1600 windows, 1 block each, 256 threads.
// q/k rows are NOT normalized in place; instead inv-norms are folded into the
// gram matrix. Output is atomicAdd-scattered into g_pred.
// smem: q[96][68] + k[96][68] + v[96][64] + g[96][36] + qn[96] + kn[96]
// --------------------------------------------------------------------------
#define ATTN_SMEM ((96*QK_STRIDE*2 + 96*64 + 96*36 + 96 + 96) * 4)

extern __shared__ float s_mem[];
__global__ __launch_bounds__(256) void attn_kernel(const float* __restrict__ temp)
{
    float* s_q  = s_mem;
    float* s_k  = s_q  + 96 * QK_STRIDE;
    float* s_v  = s_k  + 96 * QK_STRIDE;
    float* s_g  = s_v  + 96 * 64;
    float* s_qn = s_g  + 96 * 36;
    float* s_kn = s_qn + 96;

    const int tid = threadIdx.x;
    const int bid = blockIdx.x;
    const int t   = bid >> 6;        // tile 0..24
    const int win = bid & 63;        // window-in-tile
    const int r0  = c_off[t / 5] + (win >> 3) * 8;
    const int cc0 = c_off[t % 5] + (win & 7) * 8;

    // load 288x64 patch
    for (int idx = tid; idx < C3 * 64; idx += 256) {
        int ch = idx >> 6, n = idx & 63;
        float v = g_dw[ch * HWP + (r0 + (n >> 3)) * WW + cc0 + (n & 7)];
        if (ch < 96)       s_q[ch * QK_STRIDE + n] = v;
        else if (ch < 192) s_k[(ch - 96) * QK_STRIDE + n] = v;
        else               s_v[(ch - 192) * 64 + n] = v;
    }
    __syncthreads();

    // inverse L2 norms along token dim (warp per row)
    const int wid = tid >> 5, lane = tid & 31;
    for (int r = wid; r < 192; r += 8) {
        const float* row = (r < 96) ? (s_q + r * QK_STRIDE)
                                    : (s_k + (r - 96) * QK_STRIDE);
        float v0 = row[lane], v1 = row[lane + 32];
        float s = v0 * v0 + v1 * v1;
        #pragma unroll
        for (int o = 16; o; o >>= 1) s += __shfl_xor_sync(0xffffffffu, s, o);
        if (lane == 0) {
            float inv = 1.0f / fmaxf(sqrtf(s), 1e-12f);
            if (r < 96) s_qn[r] = inv; else s_kn[r - 96] = inv;
        }
    }
    __syncthreads();

    // gram: G = relu((q_hat . k_hat) * temperature), per head 32x32.
    // 64 threads per head, each computes a 4x4 block via float4 dot-64.
    if (tid < 192) {
        const int ht = tid / 64, u = tid % 64;
        const int cqr = (u >> 3) * 4;     // local q-row base
        const int ckr = (u & 7) * 4;      // local k-row base
        const int cq = ht * 32 + cqr;
        const int ck = ht * 32 + ckr;
        float acc[4][4] = {};
        #pragma unroll 4
        for (int nv = 0; nv < 16; nv++) {
            float4 qa[4], kb[4];
            #pragma unroll
            for (int i = 0; i < 4; i++)
                qa[i] = *(const float4*)&s_q[(cq + i) * QK_STRIDE + nv * 4];
            #pragma unroll
            for (int j = 0; j < 4; j++)
                kb[j] = *(const float4*)&s_k[(ck + j) * QK_STRIDE + nv * 4];
            #pragma unroll
            for (int i = 0; i < 4; i++)
                #pragma unroll
                for (int j = 0; j < 4; j++) {
                    acc[i][j] += qa[i].x * kb[j].x + qa[i].y * kb[j].y
                               + qa[i].z * kb[j].z + qa[i].w * kb[j].w;
                }
        }
        const float tmp = __ldg(&temp[ht]);
        #pragma unroll
        for (int i = 0; i < 4; i++)
            #pragma unroll
            for (int j = 0; j < 4; j++) {
                float g = acc[i][j] * s_qn[cq + i] * s_kn[ck + j] * tmp;
                s_g[(cq + i) * 36 + ckr + j] = fmaxf(g, 0.0f);
            }
    }
    __syncthreads();

    // out = G @ v, then atomicAdd into g_pred.
    // thread covers 4 channels x one full window row (y=u&7, x=0..7).
    if (tid < 192) {
        const int ht = tid / 64, u = tid % 64;
        const int cr = (u >> 3) * 4;      // local out-channel base
        const int n0 = (u & 7) * 8;
        float acc[4][8] = {};
        #pragma unroll 4
        for (int d = 0; d < 32; d++) {
            float4 va = *(const float4*)&s_v[(ht * 32 + d) * 64 + n0];
            float4 vb = *(const float4*)&s_v[(ht * 32 + d) * 64 + n0 + 4];
            #pragma unroll
            for (int i = 0; i < 4; i++) {
                float g = s_g[(ht * 32 + cr + i) * 36 + d];
                acc[i][0] += g * va.x; acc[i][1] += g * va.y;
                acc[i][2] += g * va.z; acc[i][3] += g * va.w;
                acc[i][4] += g * vb.x; acc[i][5] += g * vb.y;
                acc[i][6] += g * vb.z; acc[i][7] += g * vb.w;
            }
        }
        const int y = u & 7;
        #pragma unroll
        for (int i = 0; i < 4; i++) {
            float* dst = g_pred + (ht * 32 + cr + i) * HWP + (r0 + y) * WW + cc0;
            #pragma unroll
            for (int j = 0; j < 8; j++) atomicAdd(dst + j, acc[i][j]);
        }
    }
}

// --------------------------------------------------------------------------
// K4: out = proj_w @ (g_pred / cnt), written with (+4,+4) unroll-shift.
// Same GEMM structure as K1 (M=96).
// --------------------------------------------------------------------------
__global__ __launch_bounds__(256) void proj_gemm_kernel(
    const float* __restrict__ pw, float* __restrict__ out)
{
    __shared__ float sW[96][97];
    __shared__ float sX[96][64];
    __shared__ int   s_dst[64];
    __shared__ float s_icnt[64];

    const int tid = threadIdx.x;
    const int p0  = blockIdx.x * 64;

    if (tid < 64) {
        int p = p0 + tid;
        int h = p / WW, ww = p % WW;
        int hd = h + SHIFT; if (hd >= HH) hd -= HH;
        int wd = ww + SHIFT; if (wd >= WW) wd -= WW;
        s_dst[tid] = hd * WW + wd;
        int ch2 = 0, cw = 0;
        #pragma unroll
        for (int o = 0; o < 5; o++) {
            int off = c_off[o];
            ch2 += (off <= h  && h  < off + 64);
            cw  += (off <= ww && ww < off + 64);
        }
        s_icnt[tid] = 1.0f / (float)(ch2 * cw);
    }
    for (int i = tid; i < 96 * 96; i += 256) sW[i / 96][i % 96] = pw[i];
    __syncthreads();
    for (int i = tid; i < 96 * 64; i += 256) {
        int k = i >> 6, px = i & 63;
        sX[k][px] = g_pred[k * HWP + p0 + px] * s_icnt[px];
    }
    __syncthreads();

    const int ty = tid >> 4, tx = tid & 15;
    float acc[6][4] = {};
    #pragma unroll 4
    for (int k = 0; k < 96; k++) {
        float a[6], b[4];
        #pragma unroll
        for (int i = 0; i < 6; i++) a[i] = sW[ty + 16 * i][k];
        #pragma unroll
        for (int j = 0; j < 4; j++) b[j] = sX[k][tx + 16 * j];
        #pragma unroll
        for (int i = 0; i < 6; i++)
            #pragma unroll
            for (int j = 0; j < 4; j++)
                acc[i][j] += a[i] * b[j];
    }
    #pragma unroll
    for (int i = 0; i < 6; i++)
        #pragma unroll
        for (int j = 0; j < 4; j++)
            out[(ty + 16 * i) * HWP + s_dst[tx + 16 * j]] = acc[i][j];
}

// --------------------------------------------------------------------------
extern "C" void kernel_launch(void* const* d_in, const int* in_sizes, int n_in,
                              void* d_out, int out_size)
{
    const float* x    = (const float*)d_in[0];   // (1,96,264,264)
    const float* temp = (const float*)d_in[1];   // (3,1,1)
    const float* qkvw = (const float*)d_in[2];   // (288,96)
    const float* dww  = (const float*)d_in[3];   // (288,1,3,3)
    const float* pw   = (const float*)d_in[4];   // (96,96)
    float* out = (float*)d_out;                  // (1,96,264,264)

    zero_pred_kernel<<<(C * HWP + 255) / 256, 256>>>();
    qkv_gemm_kernel<<<dim3(HWP / 64, 3), 256>>>(x, qkvw);
    dwconv_kernel<<<dim3((HWP + 255) / 256, C3), 256>>>(dww);
    cudaFuncSetAttribute(attn_kernel,
                         cudaFuncAttributeMaxDynamicSharedMemorySize, ATTN_SMEM);
    attn_kernel<<<1600, 256, ATTN_SMEM>>>(temp);
    proj_gemm_kernel<<<HWP / 64, 256>>>(pw, out);
}

// round 2
// speedup vs baseline: 1.1200x; 1.1200x over previous
#include <cuda_runtime.h>

#define HH 264
#define WW 264
#define HWP (HH*WW)      // 69696
#define C 96
#define C3 288
#define SHIFT 4

typedef unsigned long long ull;

// ---- scratch (static device globals; allocation is forbidden) ----
__device__ float g_qkv[C3 * HWP];   // after 1x1 conv (shifted frame)
__device__ float g_dw [C3 * HWP];   // after depthwise 3x3
__device__ float g_pred[C * HWP];   // attention scatter-add accumulator

__constant__ int c_off[5] = {0, 50, 100, 150, 200};

// ---- packed fp32x2 helpers (Blackwell FFMA2: PTX-only) ----
__device__ __forceinline__ ull pack2(float x) {
    unsigned int u = __float_as_uint(x);
    ull r;
    asm("mov.b64 %0, {%1, %1};" : "=l"(r) : "r"(u));
    return r;
}
__device__ __forceinline__ void fma2(ull& d, ull a, ull b) {
    asm("fma.rn.f32x2 %0, %1, %2, %0;" : "+l"(d) : "l"(a), "l"(b));
}
__device__ __forceinline__ float2 unpack2(ull v) {
    unsigned int lo, hi;
    asm("mov.b64 {%0, %1}, %2;" : "=r"(lo), "=r"(hi) : "l"(v));
    return make_float2(__uint_as_float(lo), __uint_as_float(hi));
}

// --------------------------------------------------------------------------
// K0: zero the accumulator (float4)
// --------------------------------------------------------------------------
__global__ void zero_pred_kernel() {
    int i = blockIdx.x * blockDim.x + threadIdx.x;
    if (i < C * HWP / 4) ((float4*)g_pred)[i] = make_float4(0.f, 0.f, 0.f, 0.f);
}

// --------------------------------------------------------------------------
// K1: qkv = qkv_w @ x_shifted   (M=288, K=96, N=69696), packed f32x2.
// block: 96 oc x 64 px, 256 threads = ty(32) x tx(8).
// per thread: 3 oc x 8 px (4 pairs).
// --------------------------------------------------------------------------
__global__ __launch_bounds__(256) void qkv_gemm_kernel(
    const float* __restrict__ x, const float* __restrict__ w)
{
    __shared__ float sW[96][97];
    __shared__ float sX[96][64];
    __shared__ int   s_src[64];

    const int tid = threadIdx.x;
    const int p0  = blockIdx.x * 64;
    const int oc0 = blockIdx.y * 96;

    if (tid < 64) {
        int p = p0 + tid;
        int h = p / WW, ww = p % WW;
        int hs = h + SHIFT; if (hs >= HH) hs -= HH;
        int ws = ww + SHIFT; if (ws >= WW) ws -= WW;
        s_src[tid] = hs * WW + ws;
    }
    for (int i = tid; i < 96 * 96; i += 256)
        sW[i / 96][i % 96] = w[(oc0 + i / 96) * 96 + (i % 96)];
    __syncthreads();
    for (int i = tid; i < 96 * 64; i += 256) {
        int k = i >> 6, px = i & 63;
        sX[k][px] = x[k * HWP + s_src[px]];
    }
    __syncthreads();

    const int ty = tid >> 3, tx = tid & 7;
    ull acc[3][4] = {};
    #pragma unroll 4
    for (int k = 0; k < 96; k++) {
        ull ap[3];
        #pragma unroll
        for (int i = 0; i < 3; i++) ap[i] = pack2(sW[ty + 32 * i][k]);
        ulonglong2 b01 = *(const ulonglong2*)&sX[k][tx * 8];
        ulonglong2 b23 = *(const ulonglong2*)&sX[k][tx * 8 + 4];
        #pragma unroll
        for (int i = 0; i < 3; i++) {
            fma2(acc[i][0], ap[i], b01.x);
            fma2(acc[i][1], ap[i], b01.y);
            fma2(acc[i][2], ap[i], b23.x);
            fma2(acc[i][3], ap[i], b23.y);
        }
    }
    #pragma unroll
    for (int i = 0; i < 3; i++) {
        float* dst = &g_qkv[(oc0 + ty + 32 * i) * HWP + p0 + tx * 8];
        *(ulonglong2*)dst       = make_ulonglong2(acc[i][0], acc[i][1]);
        *(ulonglong2*)(dst + 4) = make_ulonglong2(acc[i][2], acc[i][3]);
    }
}

// --------------------------------------------------------------------------
// K2: depthwise 3x3, pad 1, 288 channels. 4 px per thread (float4 I/O).
// --------------------------------------------------------------------------
#define DW_GROUPS (HWP / 4)   // 17424
__global__ __launch_bounds__(256) void dwconv_kernel(const float* __restrict__ dww)
{
    const int c = blockIdx.y;
    const int g = blockIdx.x * 256 + threadIdx.x;
    if (g >= DW_GROUPS) return;
    const int p  = g * 4;
    const int h  = p / WW;
    const int w0 = p % WW;       // multiple of 4
    const float* in = g_qkv + c * HWP;

    float wt[9];
    #pragma unroll
    for (int i = 0; i < 9; i++) wt[i] = __ldg(&dww[c * 9 + i]);

    float o0 = 0.f, o1 = 0.f, o2 = 0.f, o3 = 0.f;
    #pragma unroll
    for (int ky = 0; ky < 3; ky++) {
        int y = h + ky - 1;
        if ((unsigned)y >= HH) continue;
        const float* base = in + y * WW + w0;
        float v0 = (w0 > 0) ? __ldg(base - 1) : 0.f;
        float4 vc = *(const float4*)base;
        float v5 = (w0 + 4 < WW) ? __ldg(base + 4) : 0.f;
        float vals[6] = {v0, vc.x, vc.y, vc.z, vc.w, v5};
        #pragma unroll
        for (int kx = 0; kx < 3; kx++) {
            float wv = wt[ky * 3 + kx];
            o0 += wv * vals[kx];
            o1 += wv * vals[kx + 1];
            o2 += wv * vals[kx + 2];
            o3 += wv * vals[kx + 3];
        }
    }
    *(float4*)&g_dw[c * HWP + p] = make_float4(o0, o1, o2, o3);
}

// --------------------------------------------------------------------------
// K3: per-(window,head) channel attention. grid (1600, 3), 128 threads.
// smem ~30.5KB -> 7 CTAs/SM. Packed f32x2 in gram + AV stages.
// --------------------------------------------------------------------------
__global__ __launch_bounds__(128) void attn_kernel(const float* __restrict__ temp)
{
    __shared__ float s_q[32 * 68];
    __shared__ float s_k[32 * 68];
    __shared__ float s_v[32 * 64];
    __shared__ float s_g[32 * 36];
    __shared__ float s_qn[32];
    __shared__ float s_kn[32];

    const int tid  = threadIdx.x;
    const int win  = blockIdx.x;          // 0..1599
    const int head = blockIdx.y;          // 0..2
    const int t    = win >> 6;
    const int w64  = win & 63;
    const int r0   = c_off[t / 5] + (w64 >> 3) * 8;
    const int cc0  = c_off[t % 5] + (w64 & 7) * 8;

    // load 96 channels (32 q, 32 k, 32 v of this head) x 64 px, float2-wide
    for (int idx = tid; idx < 96 * 32; idx += 128) {
        int ch   = idx >> 5;             // 0..95
        int pair = idx & 31;
        int r = pair >> 2, j = (pair & 3) * 2;
        int gch, soff;
        if (ch < 32)      { gch = head * 32 + ch;              soff = -1; }
        else if (ch < 64) { gch = 96 + head * 32 + (ch - 32);  soff = -2; }
        else              { gch = 192 + head * 32 + (ch - 64); soff = -3; }
        float2 v = *(const float2*)&g_dw[gch * HWP + (r0 + r) * WW + cc0 + j];
        int n = r * 8 + j;
        if (soff == -1)      *(float2*)&s_q[ch * 68 + n] = v;
        else if (soff == -2) *(float2*)&s_k[(ch - 32) * 68 + n] = v;
        else                 *(float2*)&s_v[(ch - 64) * 64 + n] = v;
    }
    __syncthreads();

    // inverse L2 norms along token dim
    if (tid < 64) {
        const float* row = (tid < 32) ? (s_q + tid * 68) : (s_k + (tid - 32) * 68);
        float s = 0.f;
        #pragma unroll
        for (int i = 0; i < 32; i++) {
            float2 v = *(const float2*)&row[2 * i];
            s += v.x * v.x + v.y * v.y;
        }
        float inv = 1.0f / fmaxf(sqrtf(s), 1e-12f);
        if (tid < 32) s_qn[tid] = inv; else s_kn[tid - 32] = inv;
    }
    __syncthreads();

    // gram: 32x32, K=64 reduced pairwise with f32x2.
    {
        const int qr = (tid >> 3) * 2;       // 2 q rows
        const int kr = (tid & 7) * 4;        // 4 k rows
        ull acc[2][4] = {};
        #pragma unroll 4
        for (int nv = 0; nv < 16; nv++) {
            ulonglong2 qa0 = *(const ulonglong2*)&s_q[qr * 68 + nv * 4];
            ulonglong2 qa1 = *(const ulonglong2*)&s_q[(qr + 1) * 68 + nv * 4];
            #pragma unroll
            for (int j = 0; j < 4; j++) {
                ulonglong2 kb = *(const ulonglong2*)&s_k[(kr + j) * 68 + nv * 4];
                fma2(acc[0][j], qa0.x, kb.x);
                fma2(acc[0][j], qa0.y, kb.y);
                fma2(acc[1][j], qa1.x, kb.x);
                fma2(acc[1][j], qa1.y, kb.y);
            }
        }
        const float tmp = __ldg(&temp[head]);
        #pragma unroll
        for (int i = 0; i < 2; i++)
            #pragma unroll
            for (int j = 0; j < 4; j++) {
                float2 p = unpack2(acc[i][j]);
                float gv = (p.x + p.y) * s_qn[qr + i] * s_kn[kr + j] * tmp;
                s_g[(qr + i) * 36 + kr + j] = fmaxf(gv, 0.0f);
            }
    }
    __syncthreads();

    // out = G @ v (f32x2 along px), atomicAdd scatter into g_pred
    {
        const int co = (tid >> 3) * 2;       // 2 out channels
        const int n0 = (tid & 7) * 8;        // 8 px (window row y = tid&7)
        ull acc[2][4] = {};
        #pragma unroll 4
        for (int d = 0; d < 32; d++) {
            ull g0 = pack2(s_g[co * 36 + d]);
            ull g1 = pack2(s_g[(co + 1) * 36 + d]);
            ulonglong2 va = *(const ulonglong2*)&s_v[d * 64 + n0];
            ulonglong2 vb = *(const ulonglong2*)&s_v[d * 64 + n0 + 4];
            fma2(acc[0][0], g0, va.x); fma2(acc[0][1], g0, va.y);
            fma2(acc[0][2], g0, vb.x); fma2(acc[0][3], g0, vb.y);
            fma2(acc[1][0], g1, va.x); fma2(acc[1][1], g1, va.y);
            fma2(acc[1][2], g1, vb.x); fma2(acc[1][3], g1, vb.y);
        }
        const int y = tid & 7;
        #pragma unroll
        for (int i = 0; i < 2; i++) {
            float* base = g_pred + (head * 32 + co + i) * HWP + (r0 + y) * WW + cc0;
            #pragma unroll
            for (int p = 0; p < 4; p++) {
                float2 v = unpack2(acc[i][p]);
                atomicAdd(base + 2 * p, v.x);
                atomicAdd(base + 2 * p + 1, v.y);
            }
        }
    }
}

// --------------------------------------------------------------------------
// K4: out = proj_w @ (g_pred / cnt), (+4,+4) unroll-shift folded into store.
// Packed f32x2, same structure as K1 with M=96.
// --------------------------------------------------------------------------
__global__ __launch_bounds__(256) void proj_gemm_kernel(
    const float* __restrict__ pw, float* __restrict__ out)
{
    __shared__ float sW[96][97];
    __shared__ float sX[96][64];
    __shared__ int   s_dst[64];
    __shared__ float s_icnt[64];

    const int tid = threadIdx.x;
    const int p0  = blockIdx.x * 64;

    if (tid < 64) {
        int p = p0 + tid;
        int h = p / WW, ww = p % WW;
        int hd = h + SHIFT; if (hd >= HH) hd -= HH;
        int wd = ww + SHIFT; if (wd >= WW) wd -= WW;
        s_dst[tid] = hd * WW + wd;
        int ch2 = 0, cw = 0;
        #pragma unroll
        for (int o = 0; o < 5; o++) {
            int off = c_off[o];
            ch2 += (off <= h  && h  < off + 64);
            cw  += (off <= ww && ww < off + 64);
        }
        s_icnt[tid] = 1.0f / (float)(ch2 * cw);
    }
    for (int i = tid; i < 96 * 96; i += 256) sW[i / 96][i % 96] = pw[i];
    __syncthreads();
    for (int i = tid; i < 96 * 64; i += 256) {
        int k = i >> 6, px = i & 63;
        sX[k][px] = g_pred[k * HWP + p0 + px] * s_icnt[px];
    }
    __syncthreads();

    const int ty = tid >> 3, tx = tid & 7;
    ull acc[3][4] = {};
    #pragma unroll 4
    for (int k = 0; k < 96; k++) {
        ull ap[3];
        #pragma unroll
        for (int i = 0; i < 3; i++) ap[i] = pack2(sW[ty + 32 * i][k]);
        ulonglong2 b01 = *(const ulonglong2*)&sX[k][tx * 8];
        ulonglong2 b23 = *(const ulonglong2*)&sX[k][tx * 8 + 4];
        #pragma unroll
        for (int i = 0; i < 3; i++) {
            fma2(acc[i][0], ap[i], b01.x);
            fma2(acc[i][1], ap[i], b01.y);
            fma2(acc[i][2], ap[i], b23.x);
            fma2(acc[i][3], ap[i], b23.y);
        }
    }
    #pragma unroll
    for (int i = 0; i < 3; i++) {
        const int oc = ty + 32 * i;
        #pragma unroll
        for (int p = 0; p < 4; p++) {
            float2 v = unpack2(acc[i][p]);
            out[oc * HWP + s_dst[tx * 8 + 2 * p]]     = v.x;
            out[oc * HWP + s_dst[tx * 8 + 2 * p + 1]] = v.y;
        }
    }
}

// --------------------------------------------------------------------------
extern "C" void kernel_launch(void* const* d_in, const int* in_sizes, int n_in,
                              void* d_out, int out_size)
{
    const float* x    = (const float*)d_in[0];   // (1,96,264,264)
    const float* temp = (const float*)d_in[1];   // (3,1,1)
    const float* qkvw = (const float*)d_in[2];   // (288,96)
    const float* dww  = (const float*)d_in[3];   // (288,1,3,3)
    const float* pw   = (const float*)d_in[4];   // (96,96)
    float* out = (float*)d_out;                  // (1,96,264,264)

    zero_pred_kernel<<<(C * HWP / 4 + 255) / 256, 256>>>();
    qkv_gemm_kernel<<<dim3(HWP / 64, 3), 256>>>(x, qkvw);
    dwconv_kernel<<<dim3((DW_GROUPS + 255) / 256, C3), 256>>>(dww);
    attn_kernel<<<dim3(1600, 3), 128>>>(temp);
    proj_gemm_kernel<<<HWP / 64, 256>>>(pw, out);
}

// round 3
// speedup vs baseline: 1.3455x; 1.2014x over previous
#include <cuda_runtime.h>

#define HH 264
#define WW 264
#define HWP (HH*WW)      // 69696
#define C 96
#define C3 288
#define SHIFT 4

typedef unsigned long long ull;

// ---- scratch (static device globals; allocation is forbidden) ----
__device__ float g_qkv[C3 * HWP];        // after 1x1 conv (shifted frame)
__device__ float g_dw [C3 * HWP];        // after depthwise 3x3
__device__ float g_out[25 * C * 4096];   // per-tile attention output
__device__ float g_wT [C * C3];          // qkv_w transposed [k][oc]
__device__ float g_pwT[C * C];           // proj_w transposed [k][oc]

__constant__ int c_off[5] = {0, 50, 100, 150, 200};

// ---- packed fp32x2 helpers (Blackwell FFMA2: PTX-only) ----
__device__ __forceinline__ ull pack2(float x) {
    unsigned int u = __float_as_uint(x);
    ull r;
    asm("mov.b64 %0, {%1, %1};" : "=l"(r) : "r"(u));
    return r;
}
__device__ __forceinline__ void fma2(ull& d, ull a, ull b) {
    asm("fma.rn.f32x2 %0, %1, %2, %0;" : "+l"(d) : "l"(a), "l"(b));
}
__device__ __forceinline__ float2 unpack2(ull v) {
    unsigned int lo, hi;
    asm("mov.b64 {%0, %1}, %2;" : "=r"(lo), "=r"(hi) : "l"(v));
    return make_float2(__uint_as_float(lo), __uint_as_float(hi));
}
__device__ __forceinline__ float4 cat2(ull a, ull b) {
    float2 x = unpack2(a), y = unpack2(b);
    return make_float4(x.x, x.y, y.x, y.y);
}

// --------------------------------------------------------------------------
// K0: transpose the two weight matrices once (tiny)
// --------------------------------------------------------------------------
__global__ void transpose_w_kernel(const float* __restrict__ qkvw,
                                   const float* __restrict__ pw)
{
    int i = blockIdx.x * 256 + threadIdx.x;
    if (i < C3 * C) { int oc = i / C, k = i % C; g_wT [k * C3 + oc] = qkvw[i]; }
    if (i < C  * C) { int oc = i / C, k = i % C; g_pwT[k * C  + oc] = pw[i]; }
}

// --------------------------------------------------------------------------
// K1: qkv = qkv_w @ x_shifted. M=96 (per blockIdx.y), N=128 px, K=96.
// 192 threads = 12 oc-groups(8 oc) x 16 px-groups(8 px). f32x2 accumulators.
// W staged transposed in smem (vector loads); X staged in 16-k chunks.
// --------------------------------------------------------------------------
#define KC 16
__global__ __launch_bounds__(192) void qkv_gemm_kernel(const float* __restrict__ x)
{
    __shared__ float sWT[C * C];       // [k][oc] stride 96
    __shared__ float sX[KC * 128];
    __shared__ int   s_src[128];

    const int tid = threadIdx.x;
    const int p0  = blockIdx.x * 128;
    const int oc0 = blockIdx.y * C;

    if (tid < 128) {
        int p = p0 + tid; if (p >= HWP) p = HWP - 1;
        int h = p / WW, ww = p % WW;
        int hs = h + SHIFT; if (hs >= HH) hs -= HH;
        int ws = ww + SHIFT; if (ws >= WW) ws -= WW;
        s_src[tid] = hs * WW + ws;
    }
    for (int i = tid; i < C * C; i += 192) {
        int k = i / C, oc = i % C;
        sWT[k * C + oc] = g_wT[k * C3 + oc0 + oc];
    }

    const int og = tid / 16, pg = tid % 16;
    ull acc[8][4] = {};

    for (int kc = 0; kc < C / KC; kc++) {
        __syncthreads();
        for (int i = tid; i < KC * 128; i += 192) {
            int k = i >> 7, px = i & 127;
            sX[k * 128 + px] = x[(kc * KC + k) * HWP + s_src[px]];
        }
        __syncthreads();
        #pragma unroll
        for (int k = 0; k < KC; k++) {
            float4 wa = *(const float4*)&sWT[(kc * KC + k) * C + og * 8];
            float4 wb = *(const float4*)&sWT[(kc * KC + k) * C + og * 8 + 4];
            ull wp[8];
            wp[0] = pack2(wa.x); wp[1] = pack2(wa.y);
            wp[2] = pack2(wa.z); wp[3] = pack2(wa.w);
            wp[4] = pack2(wb.x); wp[5] = pack2(wb.y);
            wp[6] = pack2(wb.z); wp[7] = pack2(wb.w);
            ulonglong2 xa = *(const ulonglong2*)&sX[k * 128 + pg * 8];
            ulonglong2 xb = *(const ulonglong2*)&sX[k * 128 + pg * 8 + 4];
            #pragma unroll
            for (int o = 0; o < 8; o++) {
                fma2(acc[o][0], wp[o], xa.x);
                fma2(acc[o][1], wp[o], xa.y);
                fma2(acc[o][2], wp[o], xb.x);
                fma2(acc[o][3], wp[o], xb.y);
            }
        }
    }
    if (p0 + pg * 8 < HWP) {
        #pragma unroll
        for (int o = 0; o < 8; o++) {
            float* dst = &g_qkv[(oc0 + og * 8 + o) * HWP + p0 + pg * 8];
            *(float4*)dst       = cat2(acc[o][0], acc[o][1]);
            *(float4*)(dst + 4) = cat2(acc[o][2], acc[o][3]);
        }
    }
}

// --------------------------------------------------------------------------
// K2: depthwise 3x3, pad 1, 288 channels, 8 px per thread (264 = 33*8).
// --------------------------------------------------------------------------
__global__ __launch_bounds__(256) void dwconv_kernel(const float* __restrict__ dww)
{
    const int c = blockIdx.y;
    const int g = blockIdx.x * 256 + threadIdx.x;
    if (g >= HWP / 8) return;
    const int h  = g / 33;
    const int w0 = (g % 33) * 8;
    const float* in = g_qkv + c * HWP;

    float wt[9];
    #pragma unroll
    for (int i = 0; i < 9; i++) wt[i] = __ldg(&dww[c * 9 + i]);

    float o[8] = {};
    #pragma unroll
    for (int ky = 0; ky < 3; ky++) {
        int y = h + ky - 1;
        if ((unsigned)y >= HH) continue;
        const float* b = in + y * WW + w0;
        float4 A = *(const float4*)b;
        float4 B = *(const float4*)(b + 4);
        float L = (w0 > 0) ? __ldg(b - 1) : 0.f;
        float R = (w0 + 8 < WW) ? __ldg(b + 8) : 0.f;
        float v[10] = {L, A.x, A.y, A.z, A.w, B.x, B.y, B.z, B.w, R};
        #pragma unroll
        for (int kx = 0; kx < 3; kx++) {
            float wv = wt[ky * 3 + kx];
            #pragma unroll
            for (int p = 0; p < 8; p++) o[p] += wv * v[kx + p];
        }
    }
    float* dst = g_dw + c * HWP + h * WW + w0;
    *(float4*)dst       = make_float4(o[0], o[1], o[2], o[3]);
    *(float4*)(dst + 4) = make_float4(o[4], o[5], o[6], o[7]);
}

// --------------------------------------------------------------------------
// K3: per-(window,head) channel attention. grid (1600,3), 64 threads.
// 4x4-blocked gram with xor-free additive swizzle (conflict-free), gram
// stored transposed for float4 AV loads, direct STG to per-tile g_out.
// smem ~26KB -> 8 CTAs/SM. No atomics.
// --------------------------------------------------------------------------
__global__ __launch_bounds__(64) void attn_kernel(const float* __restrict__ temp)
{
    __shared__ float s_q[32 * 68];   // swizzled; reused as s_g (32*36) after gram
    __shared__ float s_k[32 * 68];   // swizzled
    __shared__ float s_v[32 * 64];
    __shared__ float s_qn[32], s_kn[32];

    const int tid  = threadIdx.x;
    const int win  = blockIdx.x;
    const int head = blockIdx.y;
    const int t    = win >> 6;
    const int w64  = win & 63;
    const int wy = w64 >> 3, wx = w64 & 7;
    const int r0  = c_off[t / 5] + wy * 8;
    const int cc0 = c_off[t % 5] + wx * 8;

    // load 96 ch x 64 px as float2; q/k rows stored with additive chunk swizzle
    for (int i = tid; i < 96 * 32; i += 64) {
        int ch = i >> 5, pr = i & 31;
        int r = pr >> 2, j = (pr & 3) * 2;      // row 0..7, col 0/2/4/6
        int gch = (ch < 32) ? head * 32 + ch
                : (ch < 64) ? 96 + head * 32 + (ch - 32)
                            : 192 + head * 32 + (ch - 64);
        float2 v = *(const float2*)&g_dw[gch * HWP + (r0 + r) * WW + cc0 + j];
        int n = r * 8 + j;                       // logical float index 0..63
        if (ch < 64) {
            int row = ch & 31;
            float* dst = (ch < 32) ? s_q : s_k;
            int phys = (((n >> 2) + (row >> 2)) & 15) * 4 + (n & 3);
            *(float2*)&dst[row * 68 + phys] = v;
        } else {
            *(float2*)&s_v[(ch - 64) * 64 + n] = v;
        }
    }
    __syncthreads();

    // inverse L2 norms (order-agnostic: read physical layout linearly)
    {
        const float* row = (tid < 32) ? (s_q + tid * 68) : (s_k + (tid - 32) * 68);
        float s = 0.f;
        #pragma unroll
        for (int cch = 0; cch < 16; cch++) {
            float4 v = *(const float4*)&row[cch * 4];
            s += v.x * v.x + v.y * v.y + v.z * v.z + v.w * v.w;
        }
        float inv = 1.0f / fmaxf(sqrtf(s), 1e-12f);
        if (tid < 32) s_qn[tid] = inv; else s_kn[tid - 32] = inv;
    }
    __syncthreads();

    // gram: 4x4 block per thread (8 qg x 8 kg), K=64 via f32x2
    const int qg = tid >> 3, kg = tid & 7;
    const int qr = qg * 4, kr = kg * 4;
    float gv[4][4];
    {
        ull acc[4][4] = {};
        #pragma unroll 4
        for (int lc = 0; lc < 16; lc++) {
            int qp = ((lc + qg) & 15) * 4;
            int kp = ((lc + kg) & 15) * 4;
            ulonglong2 qa[4], kb[4];
            #pragma unroll
            for (int i = 0; i < 4; i++)
                qa[i] = *(const ulonglong2*)&s_q[(qr + i) * 68 + qp];
            #pragma unroll
            for (int j = 0; j < 4; j++)
                kb[j] = *(const ulonglong2*)&s_k[(kr + j) * 68 + kp];
            #pragma unroll
            for (int i = 0; i < 4; i++)
                #pragma unroll
                for (int j = 0; j < 4; j++) {
                    fma2(acc[i][j], qa[i].x, kb[j].x);
                    fma2(acc[i][j], qa[i].y, kb[j].y);
                }
        }
        const float tmp = __ldg(&temp[head]);
        #pragma unroll
        for (int i = 0; i < 4; i++)
            #pragma unroll
            for (int j = 0; j < 4; j++) {
                float2 p = unpack2(acc[i][j]);
                gv[i][j] = fmaxf((p.x + p.y) * s_qn[qr + i] * s_kn[kr + j] * tmp, 0.f);
            }
    }
    __syncthreads();                 // everyone done reading q before overlay
    float* s_g = s_q;                // overlay: G^T stored as s_g[d][c], stride 36
    #pragma unroll
    for (int j = 0; j < 4; j++)
        *(float4*)&s_g[(kr + j) * 36 + qr] =
            make_float4(gv[0][j], gv[1][j], gv[2][j], gv[3][j]);
    __syncthreads();

    // AV: out[c][n] = sum_d G[c][d] v[d][n]; thread = 4 co x 8 px
    {
        const int cog = tid >> 3, pxg = tid & 7;
        const int co = cog * 4, n0 = pxg * 8;
        ull av[4][4] = {};
        #pragma unroll 4
        for (int d = 0; d < 32; d++) {
            float4 g4 = *(const float4*)&s_g[d * 36 + co];
            ull gp[4] = {pack2(g4.x), pack2(g4.y), pack2(g4.z), pack2(g4.w)};
            ulonglong2 va = *(const ulonglong2*)&s_v[d * 64 + n0];
            ulonglong2 vb = *(const ulonglong2*)&s_v[d * 64 + n0 + 4];
            #pragma unroll
            for (int i = 0; i < 4; i++) {
                fma2(av[i][0], gp[i], va.x);
                fma2(av[i][1], gp[i], va.y);
                fma2(av[i][2], gp[i], vb.x);
                fma2(av[i][3], gp[i], vb.y);
            }
        }
        float* base = g_out + (t * 96 + head * 32 + co) * 4096
                    + (wy * 8 + pxg) * 64 + wx * 8;
        #pragma unroll
        for (int i = 0; i < 4; i++) {
            *(float4*)(base + i * 4096)     = cat2(av[i][0], av[i][1]);
            *(float4*)(base + i * 4096 + 4) = cat2(av[i][2], av[i][3]);
        }
    }
}

// --------------------------------------------------------------------------
// K4: out = proj_w @ (gathered tile avg). Same GEMM scheme as K1 (M=96,
// N=128). X-stage gathers <=4 overlapping tiles from g_out and divides by
// the analytic count. Stores with (+4,+4) unshift.
// --------------------------------------------------------------------------
__global__ __launch_bounds__(192) void proj_gemm_kernel(float* __restrict__ out)
{
    __shared__ float sWT[C * C];
    __shared__ float sX[KC * 128];
    __shared__ int   s_toff[128 * 4];
    __shared__ int   s_dst[128];
    __shared__ float s_icnt[128];

    const int tid = threadIdx.x;
    const int p0  = blockIdx.x * 128;

    if (tid < 128) {
        int p = p0 + tid; if (p >= HWP) p = HWP - 1;
        int h = p / WW, ww = p % WW;
        int hd = h + SHIFT; if (hd >= HH) hd -= HH;
        int wd = ww + SHIFT; if (wd >= WW) wd -= WW;
        s_dst[tid] = hd * WW + wd;
        int rt[2], ct[2], nr = 0, nc = 0;
        #pragma unroll
        for (int o = 0; o < 5; o++) {
            int off = c_off[o];
            if (off <= h  && h  < off + 64) rt[nr++] = o;
            if (off <= ww && ww < off + 64) ct[nc++] = o;
        }
        #pragma unroll
        for (int m = 0; m < 4; m++) s_toff[tid * 4 + m] = -1;
        int m = 0;
        for (int a = 0; a < nr; a++)
            for (int b = 0; b < nc; b++) {
                int tt = rt[a] * 5 + ct[b];
                s_toff[tid * 4 + m++] = tt * (96 * 4096)
                    + (h - c_off[rt[a]]) * 64 + (ww - c_off[ct[b]]);
            }
        s_icnt[tid] = 1.0f / (float)(nr * nc);
    }
    for (int i = tid; i < C * C; i += 192) sWT[i] = g_pwT[i];

    const int og = tid / 16, pg = tid % 16;
    ull acc[8][4] = {};

    for (int kc = 0; kc < C / KC; kc++) {
        __syncthreads();
        for (int i = tid; i < KC * 128; i += 192) {
            int k = i >> 7, px = i & 127;
            int cch = (kc * KC + k) * 4096;
            float s = 0.f;
            #pragma unroll
            for (int m = 0; m < 4; m++) {
                int off = s_toff[px * 4 + m];
                if (off >= 0) s += g_out[off + cch];
            }
            sX[k * 128 + px] = s * s_icnt[px];
        }
        __syncthreads();
        #pragma unroll
        for (int k = 0; k < KC; k++) {
            float4 wa = *(const float4*)&sWT[(kc * KC + k) * C + og * 8];
            float4 wb = *(const float4*)&sWT[(kc * KC + k) * C + og * 8 + 4];
            ull wp[8];
            wp[0] = pack2(wa.x); wp[1] = pack2(wa.y);
            wp[2] = pack2(wa.z); wp[3] = pack2(wa.w);
            wp[4] = pack2(wb.x); wp[5] = pack2(wb.y);
            wp[6] = pack2(wb.z); wp[7] = pack2(wb.w);
            ulonglong2 xa = *(const ulonglong2*)&sX[k * 128 + pg * 8];
            ulonglong2 xb = *(const ulonglong2*)&sX[k * 128 + pg * 8 + 4];
            #pragma unroll
            for (int o = 0; o < 8; o++) {
                fma2(acc[o][0], wp[o], xa.x);
                fma2(acc[o][1], wp[o], xa.y);
                fma2(acc[o][2], wp[o], xb.x);
                fma2(acc[o][3], wp[o], xb.y);
            }
        }
    }
    if (p0 + pg * 8 < HWP) {
        #pragma unroll
        for (int o = 0; o < 8; o++) {
            const int oc = og * 8 + o;
            float4 v0 = cat2(acc[o][0], acc[o][1]);
            float4 v1 = cat2(acc[o][2], acc[o][3]);
            float vv[8] = {v0.x, v0.y, v0.z, v0.w, v1.x, v1.y, v1.z, v1.w};
            #pragma unroll
            for (int j = 0; j < 8; j++)
                out[oc * HWP + s_dst[pg * 8 + j]] = vv[j];
        }
    }
}

// --------------------------------------------------------------------------
extern "C" void kernel_launch(void* const* d_in, const int* in_sizes, int n_in,
                              void* d_out, int out_size)
{
    const float* x    = (const float*)d_in[0];   // (1,96,264,264)
    const float* temp = (const float*)d_in[1];   // (3,1,1)
    const float* qkvw = (const float*)d_in[2];   // (288,96)
    const float* dww  = (const float*)d_in[3];   // (288,1,3,3)
    const float* pw   = (const float*)d_in[4];   // (96,96)
    float* out = (float*)d_out;                  // (1,96,264,264)

    transpose_w_kernel<<<(C3 * C + 255) / 256, 256>>>(qkvw, pw);
    qkv_gemm_kernel<<<dim3((HWP + 127) / 128, 3), 192>>>(x);
    dwconv_kernel<<<dim3((HWP / 8 + 255) / 256, C3), 256>>>(dww);
    attn_kernel<<<dim3(1600, 3), 64>>>(temp);
    proj_gemm_kernel<<<(HWP + 127) / 128, 192>>>(out);
}

// round 5
// speedup vs baseline: 1.4243x; 1.0585x over previous
#include <cuda_runtime.h>
#include <cstdint>

#define HH 264
#define WW 264
#define HWP (HH*WW)      // 69696
#define C 96
#define C3 288
#define SHIFT 4

typedef unsigned long long ull;

// ---- scratch (static device globals; allocation is forbidden) ----
__device__ float g_qkv[C3 * HWP];        // after 1x1 conv (shifted frame)
__device__ float g_dw [C3 * HWP];        // after depthwise 3x3
__device__ float g_out[25 * C * 4096];   // per-tile attention output
__device__ float g_wT [C * C3];          // qkv_w transposed [k][oc]
__device__ float g_pwT[C * C];           // proj_w transposed [k][oc]

__constant__ int c_off[5] = {0, 50, 100, 150, 200};

// ---- packed fp32x2 helpers (Blackwell FFMA2: PTX-only) ----
__device__ __forceinline__ ull pack2(float x) {
    unsigned int u = __float_as_uint(x);
    ull r;
    asm("mov.b64 %0, {%1, %1};" : "=l"(r) : "r"(u));
    return r;
}
__device__ __forceinline__ void fma2(ull& d, ull a, ull b) {
    asm("fma.rn.f32x2 %0, %1, %2, %0;" : "+l"(d) : "l"(a), "l"(b));
}
__device__ __forceinline__ float2 unpack2(ull v) {
    unsigned int lo, hi;
    asm("mov.b64 {%0, %1}, %2;" : "=r"(lo), "=r"(hi) : "l"(v));
    return make_float2(__uint_as_float(lo), __uint_as_float(hi));
}
__device__ __forceinline__ float4 cat2(ull a, ull b) {
    float2 x = unpack2(a), y = unpack2(b);
    return make_float4(x.x, x.y, y.x, y.y);
}

// --------------------------------------------------------------------------
// K0: transpose the two weight matrices once (tiny)
// --------------------------------------------------------------------------
__global__ void transpose_w_kernel(const float* __restrict__ qkvw,
                                   const float* __restrict__ pw)
{
    int i = blockIdx.x * 256 + threadIdx.x;
    if (i < C3 * C) { int oc = i / C, k = i % C; g_wT [k * C3 + oc] = qkvw[i]; }
    if (i < C  * C) { int oc = i / C, k = i % C; g_pwT[k * C  + oc] = pw[i]; }
}

// --------------------------------------------------------------------------
// K1: qkv = qkv_w @ x_shifted. M=96 (per blockIdx.y), N=128 px, K=96.
// 192 threads = 12 oc-groups(8 oc) x 16 px-groups(8 px). f32x2 accumulators.
// --------------------------------------------------------------------------
#define KC 16
__global__ __launch_bounds__(192) void qkv_gemm_kernel(const float* __restrict__ x)
{
    __shared__ float sWT[C * C];       // [k][oc] stride 96
    __shared__ float sX[KC * 128];
    __shared__ int   s_src[128];

    const int tid = threadIdx.x;
    const int p0  = blockIdx.x * 128;
    const int oc0 = blockIdx.y * C;

    if (tid < 128) {
        int p = p0 + tid; if (p >= HWP) p = HWP - 1;
        int h = p / WW, ww = p % WW;
        int hs = h + SHIFT; if (hs >= HH) hs -= HH;
        int ws = ww + SHIFT; if (ws >= WW) ws -= WW;
        s_src[tid] = hs * WW + ws;
    }
    for (int i = tid; i < C * C; i += 192) {
        int k = i / C, oc = i % C;
        sWT[k * C + oc] = g_wT[k * C3 + oc0 + oc];
    }

    const int og = tid / 16, pg = tid % 16;
    ull acc[8][4] = {};

    for (int kc = 0; kc < C / KC; kc++) {
        __syncthreads();
        for (int i = tid; i < KC * 128; i += 192) {
            int k = i >> 7, px = i & 127;
            sX[k * 128 + px] = x[(kc * KC + k) * HWP + s_src[px]];
        }
        __syncthreads();
        #pragma unroll
        for (int k = 0; k < KC; k++) {
            float4 wa = *(const float4*)&sWT[(kc * KC + k) * C + og * 8];
            float4 wb = *(const float4*)&sWT[(kc * KC + k) * C + og * 8 + 4];
            ull wp[8];
            wp[0] = pack2(wa.x); wp[1] = pack2(wa.y);
            wp[2] = pack2(wa.z); wp[3] = pack2(wa.w);
            wp[4] = pack2(wb.x); wp[5] = pack2(wb.y);
            wp[6] = pack2(wb.z); wp[7] = pack2(wb.w);
            ulonglong2 xa = *(const ulonglong2*)&sX[k * 128 + pg * 8];
            ulonglong2 xb = *(const ulonglong2*)&sX[k * 128 + pg * 8 + 4];
            #pragma unroll
            for (int o = 0; o < 8; o++) {
                fma2(acc[o][0], wp[o], xa.x);
                fma2(acc[o][1], wp[o], xa.y);
                fma2(acc[o][2], wp[o], xb.x);
                fma2(acc[o][3], wp[o], xb.y);
            }
        }
    }
    if (p0 + pg * 8 < HWP) {
        #pragma unroll
        for (int o = 0; o < 8; o++) {
            float* dst = &g_qkv[(oc0 + og * 8 + o) * HWP + p0 + pg * 8];
            *(float4*)dst       = cat2(acc[o][0], acc[o][1]);
            *(float4*)(dst + 4) = cat2(acc[o][2], acc[o][3]);
        }
    }
}

// --------------------------------------------------------------------------
// K2: depthwise 3x3, pad 1, 288 channels, 8 px per thread (264 = 33*8).
// --------------------------------------------------------------------------
__global__ __launch_bounds__(256) void dwconv_kernel(const float* __restrict__ dww)
{
    const int c = blockIdx.y;
    const int g = blockIdx.x * 256 + threadIdx.x;
    if (g >= HWP / 8) return;
    const int h  = g / 33;
    const int w0 = (g % 33) * 8;
    const float* in = g_qkv + c * HWP;

    float wt[9];
    #pragma unroll
    for (int i = 0; i < 9; i++) wt[i] = __ldg(&dww[c * 9 + i]);

    float o[8] = {};
    #pragma unroll
    for (int ky = 0; ky < 3; ky++) {
        int y = h + ky - 1;
        if ((unsigned)y >= HH) continue;
        const float* b = in + y * WW + w0;
        float4 A = *(const float4*)b;
        float4 B = *(const float4*)(b + 4);
        float L = (w0 > 0) ? __ldg(b - 1) : 0.f;
        float R = (w0 + 8 < WW) ? __ldg(b + 8) : 0.f;
        float v[10] = {L, A.x, A.y, A.z, A.w, B.x, B.y, B.z, B.w, R};
        #pragma unroll
        for (int kx = 0; kx < 3; kx++) {
            float wv = wt[ky * 3 + kx];
            #pragma unroll
            for (int pp = 0; pp < 8; pp++) o[pp] += wv * v[kx + pp];
        }
    }
    float* dst = g_dw + c * HWP + h * WW + w0;
    *(float4*)dst       = make_float4(o[0], o[1], o[2], o[3]);
    *(float4*)(dst + 4) = make_float4(o[4], o[5], o[6], o[7]);
}

// --------------------------------------------------------------------------
// K3: per-(window,head) channel attention. grid (1600,3), 64 threads.
// q/k in swizzled smem; v read straight from g_dw in the AV stage (8B LDG).
// smem ~17.6KB; launch_bounds(64,10) caps regs for ~10 CTAs/SM.
// --------------------------------------------------------------------------
__global__ __launch_bounds__(64, 10) void attn_kernel(const float* __restrict__ temp)
{
    __shared__ float s_q[32 * 68];   // swizzled; reused as s_g (32*36) after gram
    __shared__ float s_k[32 * 68];   // swizzled
    __shared__ float s_qn[32], s_kn[32];

    const int tid  = threadIdx.x;
    const int win  = blockIdx.x;
    const int head = blockIdx.y;
    const int t    = win >> 6;
    const int w64  = win & 63;
    const int wy = w64 >> 3, wx = w64 & 7;
    const int r0  = c_off[t / 5] + wy * 8;
    const int cc0 = c_off[t % 5] + wx * 8;

    // load q,k (64 ch x 64 px) as float2 with additive chunk swizzle
    for (int i = tid; i < 64 * 32; i += 64) {
        int ch = i >> 5, pr = i & 31;
        int r = pr >> 2, j = (pr & 3) * 2;
        int gch = (ch < 32) ? head * 32 + ch : 96 + head * 32 + (ch - 32);
        float2 v = *(const float2*)&g_dw[gch * HWP + (r0 + r) * WW + cc0 + j];
        int n = r * 8 + j;
        int row = ch & 31;
        float* dst = (ch < 32) ? s_q : s_k;
        int phys = (((n >> 2) + (row >> 2)) & 15) * 4 + (n & 3);
        *(float2*)&dst[row * 68 + phys] = v;
    }
    __syncthreads();

    // inverse L2 norms (order-agnostic: physical layout is a permutation)
    {
        const float* row = (tid < 32) ? (s_q + tid * 68) : (s_k + (tid - 32) * 68);
        float s = 0.f;
        #pragma unroll
        for (int cch = 0; cch < 16; cch++) {
            float4 v = *(const float4*)&row[cch * 4];
            s += v.x * v.x + v.y * v.y + v.z * v.z + v.w * v.w;
        }
        float inv = 1.0f / fmaxf(sqrtf(s), 1e-12f);
        if (tid < 32) s_qn[tid] = inv; else s_kn[tid - 32] = inv;
    }
    __syncthreads();

    // gram: 4x4 block per thread (8 qg x 8 kg), K=64 via f32x2
    const int qg = tid >> 3, kg = tid & 7;
    const int qr = qg * 4, kr = kg * 4;
    float gv[4][4];
    {
        ull acc[4][4] = {};
        #pragma unroll 4
        for (int lc = 0; lc < 16; lc++) {
            int qp = ((lc + qg) & 15) * 4;
            int kp = ((lc + kg) & 15) * 4;
            ulonglong2 qa[4], kb[4];
            #pragma unroll
            for (int i = 0; i < 4; i++)
                qa[i] = *(const ulonglong2*)&s_q[(qr + i) * 68 + qp];
            #pragma unroll
            for (int j = 0; j < 4; j++)
                kb[j] = *(const ulonglong2*)&s_k[(kr + j) * 68 + kp];
            #pragma unroll
            for (int i = 0; i < 4; i++)
                #pragma unroll
                for (int j = 0; j < 4; j++) {
                    fma2(acc[i][j], qa[i].x, kb[j].x);
                    fma2(acc[i][j], qa[i].y, kb[j].y);
                }
        }
        const float tmp = __ldg(&temp[head]);
        #pragma unroll
        for (int i = 0; i < 4; i++)
            #pragma unroll
            for (int j = 0; j < 4; j++) {
                float2 pr = unpack2(acc[i][j]);
                gv[i][j] = fmaxf((pr.x + pr.y) * s_qn[qr + i] * s_kn[kr + j] * tmp, 0.f);
            }
    }
    __syncthreads();
    float* s_g = s_q;                // overlay: G^T as s_g[d][c], stride 36
    #pragma unroll
    for (int j = 0; j < 4; j++)
        *(float4*)&s_g[(kr + j) * 36 + qr] =
            make_float4(gv[0][j], gv[1][j], gv[2][j], gv[3][j]);
    __syncthreads();

    // AV: out[c][n] = sum_d G[c][d] v[d][n]; v straight from g_dw (8B loads)
    {
        const int cog = tid >> 3, pxg = tid & 7;
        const int co = cog * 4;
        const float* vbase = g_dw + (size_t)(192 + head * 32) * HWP
                           + (r0 + pxg) * WW + cc0;
        ull av[4][4] = {};
        #pragma unroll 4
        for (int d = 0; d < 32; d++) {
            float4 g4 = *(const float4*)&s_g[d * 36 + co];
            ull gp[4] = {pack2(g4.x), pack2(g4.y), pack2(g4.z), pack2(g4.w)};
            const ull* vr = (const ull*)(vbase + (size_t)d * HWP);
            ull v0 = vr[0], v1 = vr[1], v2 = vr[2], v3 = vr[3];
            #pragma unroll
            for (int i = 0; i < 4; i++) {
                fma2(av[i][0], gp[i], v0);
                fma2(av[i][1], gp[i], v1);
                fma2(av[i][2], gp[i], v2);
                fma2(av[i][3], gp[i], v3);
            }
        }
        float* base = g_out + (t * 96 + head * 32 + co) * 4096
                    + (wy * 8 + pxg) * 64 + wx * 8;
        #pragma unroll
        for (int i = 0; i < 4; i++) {
            *(float4*)(base + i * 4096)     = cat2(av[i][0], av[i][1]);
            *(float4*)(base + i * 4096 + 4) = cat2(av[i][2], av[i][3]);
        }
    }
}

// --------------------------------------------------------------------------
// K4: out = proj_w @ (gathered tile avg), f32x2, (+4,+4) unshift on store.
// --------------------------------------------------------------------------
__global__ __launch_bounds__(192) void proj_gemm_kernel(float* __restrict__ out)
{
    __shared__ float sWT[C * C];
    __shared__ float sX[KC * 128];
    __shared__ int   s_toff[128 * 4];
    __shared__ int   s_dst[128];
    __shared__ float s_icnt[128];

    const int tid = threadIdx.x;
    const int p0  = blockIdx.x * 128;

    if (tid < 128) {
        int p = p0 + tid; if (p >= HWP) p = HWP - 1;
        int h = p / WW, ww = p % WW;
        int hd = h + SHIFT; if (hd >= HH) hd -= HH;
        int wd = ww + SHIFT; if (wd >= WW) wd -= WW;
        s_dst[tid] = hd * WW + wd;
        int rt[2], ct[2], nr = 0, nc = 0;
        #pragma unroll
        for (int o = 0; o < 5; o++) {
            int off = c_off[o];
            if (off <= h  && h  < off + 64) rt[nr++] = o;
            if (off <= ww && ww < off + 64) ct[nc++] = o;
        }
        #pragma unroll
        for (int m = 0; m < 4; m++) s_toff[tid * 4 + m] = -1;
        int m = 0;
        for (int a = 0; a < nr; a++)
            for (int b = 0; b < nc; b++) {
                int tt = rt[a] * 5 + ct[b];
                s_toff[tid * 4 + m++] = tt * (96 * 4096)
                    + (h - c_off[rt[a]]) * 64 + (ww - c_off[ct[b]]);
            }
        s_icnt[tid] = 1.0f / (float)(nr * nc);
    }
    for (int i = tid; i < C * C; i += 192) sWT[i] = g_pwT[i];

    const int og = tid / 16, pg = tid % 16;
    ull acc[8][4] = {};

    for (int kc = 0; kc < C / KC; kc++) {
        __syncthreads();
        for (int i = tid; i < KC * 128; i += 192) {
            int k = i >> 7, px = i & 127;
            int cch = (kc * KC + k) * 4096;
            float s = 0.f;
            #pragma unroll
            for (int m = 0; m < 4; m++) {
                int off = s_toff[px * 4 + m];
                if (off >= 0) s += g_out[off + cch];
            }
            sX[k * 128 + px] = s * s_icnt[px];
        }
        __syncthreads();
        #pragma unroll
        for (int k = 0; k < KC; k++) {
            float4 wa = *(const float4*)&sWT[(kc * KC + k) * C + og * 8];
            float4 wb = *(const float4*)&sWT[(kc * KC + k) * C + og * 8 + 4];
            ull wp[8];
            wp[0] = pack2(wa.x); wp[1] = pack2(wa.y);
            wp[2] = pack2(wa.z); wp[3] = pack2(wa.w);
            wp[4] = pack2(wb.x); wp[5] = pack2(wb.y);
            wp[6] = pack2(wb.z); wp[7] = pack2(wb.w);
            ulonglong2 xa = *(const ulonglong2*)&sX[k * 128 + pg * 8];
            ulonglong2 xb = *(const ulonglong2*)&sX[k * 128 + pg * 8 + 4];
            #pragma unroll
            for (int o = 0; o < 8; o++) {
                fma2(acc[o][0], wp[o], xa.x);
                fma2(acc[o][1], wp[o], xa.y);
                fma2(acc[o][2], wp[o], xb.x);
                fma2(acc[o][3], wp[o], xb.y);
            }
        }
    }
    if (p0 + pg * 8 < HWP) {
        #pragma unroll
        for (int o = 0; o < 8; o++) {
            const int oc = og * 8 + o;
            float4 v0 = cat2(acc[o][0], acc[o][1]);
            float4 v1 = cat2(acc[o][2], acc[o][3]);
            float vv[8] = {v0.x, v0.y, v0.z, v0.w, v1.x, v1.y, v1.z, v1.w};
            #pragma unroll
            for (int j = 0; j < 8; j++)
                out[oc * HWP + s_dst[pg * 8 + j]] = vv[j];
        }
    }
}

// --------------------------------------------------------------------------
extern "C" void kernel_launch(void* const* d_in, const int* in_sizes, int n_in,
                              void* d_out, int out_size)
{
    const float* x    = (const float*)d_in[0];   // (1,96,264,264)
    const float* temp = (const float*)d_in[1];   // (3,1,1)
    const float* qkvw = (const float*)d_in[2];   // (288,96)
    const float* dww  = (const float*)d_in[3];   // (288,1,3,3)
    const float* pw   = (const float*)d_in[4];   // (96,96)
    float* out = (float*)d_out;                  // (1,96,264,264)

    transpose_w_kernel<<<(C3 * C + 255) / 256, 256>>>(qkvw, pw);
    qkv_gemm_kernel<<<dim3((HWP + 127) / 128, 3), 192>>>(x);
    dwconv_kernel<<<dim3((HWP / 8 + 255) / 256, C3), 256>>>(dww);
    attn_kernel<<<dim3(1600, 3), 64>>>(temp);
    proj_gemm_kernel<<<(HWP + 127) / 128, 192>>>(out);
}

// round 6
// speedup vs baseline: 1.5119x; 1.0615x over previous
#include <cuda_runtime.h>
#include <cstdint>

#define HH 264
#define WW 264
#define HWP (HH*WW)      // 69696
#define C 96
#define C3 288
#define SHIFT 4

typedef unsigned long long ull;

// ---- scratch (static device globals; allocation is forbidden) ----
__device__ float g_qkv[C3 * HWP];        // after 1x1 conv (shifted frame)
__device__ float g_dw [C3 * HWP];        // after depthwise 3x3
__device__ float g_out[25 * C * 4096];   // per-tile attention output
__device__ float g_wT [C * C3];          // qkv_w transposed [k][oc]
__device__ float g_pwT[C * C];           // proj_w transposed [k][oc]

__constant__ int c_off[5] = {0, 50, 100, 150, 200};

// ---- packed fp32x2 helpers (Blackwell FFMA2: PTX-only) ----
__device__ __forceinline__ ull pack2(float x) {
    unsigned int u = __float_as_uint(x);
    ull r;
    asm("mov.b64 %0, {%1, %1};" : "=l"(r) : "r"(u));
    return r;
}
__device__ __forceinline__ void fma2(ull& d, ull a, ull b) {
    asm("fma.rn.f32x2 %0, %1, %2, %0;" : "+l"(d) : "l"(a), "l"(b));
}
__device__ __forceinline__ float2 unpack2(ull v) {
    unsigned int lo, hi;
    asm("mov.b64 {%0, %1}, %2;" : "=r"(lo), "=r"(hi) : "l"(v));
    return make_float2(__uint_as_float(lo), __uint_as_float(hi));
}
__device__ __forceinline__ float4 cat2(ull a, ull b) {
    float2 x = unpack2(a), y = unpack2(b);
    return make_float4(x.x, x.y, y.x, y.y);
}

// --------------------------------------------------------------------------
// K0: transpose the two weight matrices once (tiny)
// --------------------------------------------------------------------------
__global__ void transpose_w_kernel(const float* __restrict__ qkvw,
                                   const float* __restrict__ pw)
{
    int i = blockIdx.x * 256 + threadIdx.x;
    if (i < C3 * C) { int oc = i / C, k = i % C; g_wT [k * C3 + oc] = qkvw[i]; }
    if (i < C  * C) { int oc = i / C, k = i % C; g_pwT[k * C  + oc] = pw[i]; }
}

// --------------------------------------------------------------------------
// K1: qkv = qkv_w @ x_shifted. M=96 (per blockIdx.y), N=128 px, K=96.
// 192 threads = 12 oc-groups(8 oc) x 16 px-groups(8 px). f32x2 accumulators.
// Register-prefetch pipeline: next K-chunk LDGs overlap current compute.
// --------------------------------------------------------------------------
#define KC 16
#define PFN 11    // ceil(KC*128 / 192)
__global__ __launch_bounds__(192) void qkv_gemm_kernel(const float* __restrict__ x)
{
    __shared__ float sWT[C * C];       // [k][oc] stride 96
    __shared__ float sX[KC * 128];
    __shared__ int   s_src[128];

    const int tid = threadIdx.x;
    const int p0  = blockIdx.x * 128;
    const int oc0 = blockIdx.y * C;

    if (tid < 128) {
        int p = p0 + tid; if (p >= HWP) p = HWP - 1;
        int h = p / WW, ww = p % WW;
        int hs = h + SHIFT; if (hs >= HH) hs -= HH;
        int ws = ww + SHIFT; if (ws >= WW) ws -= WW;
        s_src[tid] = hs * WW + ws;
    }
    for (int i = tid; i < C * C; i += 192) {
        int k = i / C, oc = i % C;
        sWT[k * C + oc] = g_wT[k * C3 + oc0 + oc];
    }
    __syncthreads();   // s_src ready for prefetch

    const int og = tid / 16, pg = tid % 16;
    ull acc[8][4] = {};
    float pf[PFN];

    // prefetch chunk 0
    #pragma unroll
    for (int j = 0; j < PFN; j++) {
        int idx = tid + j * 192;
        if (idx < KC * 128)
            pf[j] = x[((idx >> 7)) * HWP + s_src[idx & 127]];
    }

    for (int kc = 0; kc < C / KC; kc++) {
        __syncthreads();                    // previous compute done with sX
        #pragma unroll
        for (int j = 0; j < PFN; j++) {
            int idx = tid + j * 192;
            if (idx < KC * 128) sX[idx] = pf[j];
        }
        __syncthreads();
        if (kc + 1 < C / KC) {              // issue next chunk's LDGs now
            #pragma unroll
            for (int j = 0; j < PFN; j++) {
                int idx = tid + j * 192;
                if (idx < KC * 128)
                    pf[j] = x[((kc + 1) * KC + (idx >> 7)) * HWP + s_src[idx & 127]];
            }
        }
        #pragma unroll
        for (int k = 0; k < KC; k++) {
            float4 wa = *(const float4*)&sWT[(kc * KC + k) * C + og * 8];
            float4 wb = *(const float4*)&sWT[(kc * KC + k) * C + og * 8 + 4];
            ull wp[8];
            wp[0] = pack2(wa.x); wp[1] = pack2(wa.y);
            wp[2] = pack2(wa.z); wp[3] = pack2(wa.w);
            wp[4] = pack2(wb.x); wp[5] = pack2(wb.y);
            wp[6] = pack2(wb.z); wp[7] = pack2(wb.w);
            ulonglong2 xa = *(const ulonglong2*)&sX[k * 128 + pg * 8];
            ulonglong2 xb = *(const ulonglong2*)&sX[k * 128 + pg * 8 + 4];
            #pragma unroll
            for (int o = 0; o < 8; o++) {
                fma2(acc[o][0], wp[o], xa.x);
                fma2(acc[o][1], wp[o], xa.y);
                fma2(acc[o][2], wp[o], xb.x);
                fma2(acc[o][3], wp[o], xb.y);
            }
        }
    }
    if (p0 + pg * 8 < HWP) {
        #pragma unroll
        for (int o = 0; o < 8; o++) {
            float* dst = &g_qkv[(oc0 + og * 8 + o) * HWP + p0 + pg * 8];
            *(float4*)dst       = cat2(acc[o][0], acc[o][1]);
            *(float4*)(dst + 4) = cat2(acc[o][2], acc[o][3]);
        }
    }
}

// --------------------------------------------------------------------------
// K2: depthwise 3x3, pad 1, 288 channels, 8 px per thread (264 = 33*8).
// --------------------------------------------------------------------------
__global__ __launch_bounds__(256) void dwconv_kernel(const float* __restrict__ dww)
{
    const int c = blockIdx.y;
    const int g = blockIdx.x * 256 + threadIdx.x;
    if (g >= HWP / 8) return;
    const int h  = g / 33;
    const int w0 = (g % 33) * 8;
    const float* in = g_qkv + c * HWP;

    float wt[9];
    #pragma unroll
    for (int i = 0; i < 9; i++) wt[i] = __ldg(&dww[c * 9 + i]);

    float o[8] = {};
    #pragma unroll
    for (int ky = 0; ky < 3; ky++) {
        int y = h + ky - 1;
        if ((unsigned)y >= HH) continue;
        const float* b = in + y * WW + w0;
        float4 A = *(const float4*)b;
        float4 B = *(const float4*)(b + 4);
        float L = (w0 > 0) ? __ldg(b - 1) : 0.f;
        float R = (w0 + 8 < WW) ? __ldg(b + 8) : 0.f;
        float v[10] = {L, A.x, A.y, A.z, A.w, B.x, B.y, B.z, B.w, R};
        #pragma unroll
        for (int kx = 0; kx < 3; kx++) {
            float wv = wt[ky * 3 + kx];
            #pragma unroll
            for (int pp = 0; pp < 8; pp++) o[pp] += wv * v[kx + pp];
        }
    }
    float* dst = g_dw + c * HWP + h * WW + w0;
    *(float4*)dst       = make_float4(o[0], o[1], o[2], o[3]);
    *(float4*)(dst + 4) = make_float4(o[4], o[5], o[6], o[7]);
}

// --------------------------------------------------------------------------
// K3: per-(window,head) channel attention. grid (1600,3), 64 threads.
// q/k in swizzled smem; after gram, v staged ONCE into the dead s_k region
// (kills the 8x duplicated LDG traffic that made AV L1tex-bound).
// smem ~17.6KB; launch_bounds(64,10) -> ~10 CTAs/SM.
// --------------------------------------------------------------------------
__global__ __launch_bounds__(64, 10) void attn_kernel(const float* __restrict__ temp)
{
    __shared__ float s_q[32 * 68];   // swizzled; reused as s_g (32*36) after gram
    __shared__ float s_k[32 * 68];   // swizzled; reused as s_v (32*64) after gram
    __shared__ float s_qn[32], s_kn[32];

    const int tid  = threadIdx.x;
    const int win  = blockIdx.x;
    const int head = blockIdx.y;
    const int t    = win >> 6;
    const int w64  = win & 63;
    const int wy = w64 >> 3, wx = w64 & 7;
    const int r0  = c_off[t / 5] + wy * 8;
    const int cc0 = c_off[t % 5] + wx * 8;

    // load q,k (64 ch x 64 px) as float2 with additive chunk swizzle
    for (int i = tid; i < 64 * 32; i += 64) {
        int ch = i >> 5, pr = i & 31;
        int r = pr >> 2, j = (pr & 3) * 2;
        int gch = (ch < 32) ? head * 32 + ch : 96 + head * 32 + (ch - 32);
        float2 v = *(const float2*)&g_dw[gch * HWP + (r0 + r) * WW + cc0 + j];
        int n = r * 8 + j;
        int row = ch & 31;
        float* dst = (ch < 32) ? s_q : s_k;
        int phys = (((n >> 2) + (row >> 2)) & 15) * 4 + (n & 3);
        *(float2*)&dst[row * 68 + phys] = v;
    }
    __syncthreads();

    // inverse L2 norms (order-agnostic: physical layout is a permutation)
    {
        const float* row = (tid < 32) ? (s_q + tid * 68) : (s_k + (tid - 32) * 68);
        float s = 0.f;
        #pragma unroll
        for (int cch = 0; cch < 16; cch++) {
            float4 v = *(const float4*)&row[cch * 4];
            s += v.x * v.x + v.y * v.y + v.z * v.z + v.w * v.w;
        }
        float inv = 1.0f / fmaxf(sqrtf(s), 1e-12f);
        if (tid < 32) s_qn[tid] = inv; else s_kn[tid - 32] = inv;
    }
    __syncthreads();

    // gram: 4x4 block per thread (8 qg x 8 kg), K=64 via f32x2
    const int qg = tid >> 3, kg = tid & 7;
    const int qr = qg * 4, kr = kg * 4;
    float gv[4][4];
    {
        ull acc[4][4] = {};
        #pragma unroll 4
        for (int lc = 0; lc < 16; lc++) {
            int qp = ((lc + qg) & 15) * 4;
            int kp = ((lc + kg) & 15) * 4;
            ulonglong2 qa[4], kb[4];
            #pragma unroll
            for (int i = 0; i < 4; i++)
                qa[i] = *(const ulonglong2*)&s_q[(qr + i) * 68 + qp];
            #pragma unroll
            for (int j = 0; j < 4; j++)
                kb[j] = *(const ulonglong2*)&s_k[(kr + j) * 68 + kp];
            #pragma unroll
            for (int i = 0; i < 4; i++)
                #pragma unroll
                for (int j = 0; j < 4; j++) {
                    fma2(acc[i][j], qa[i].x, kb[j].x);
                    fma2(acc[i][j], qa[i].y, kb[j].y);
                }
        }
        const float tmp = __ldg(&temp[head]);
        #pragma unroll
        for (int i = 0; i < 4; i++)
            #pragma unroll
            for (int j = 0; j < 4; j++) {
                float2 pr = unpack2(acc[i][j]);
                gv[i][j] = fmaxf((pr.x + pr.y) * s_qn[qr + i] * s_kn[kr + j] * tmp, 0.f);
            }
    }
    __syncthreads();                 // all reads of s_q/s_k done
    float* s_g = s_q;                // overlay: G^T as s_g[d][c], stride 36
    float* s_v = s_k;                // overlay: v as s_v[d][n], stride 64
    #pragma unroll
    for (int j = 0; j < 4; j++)
        *(float4*)&s_g[(kr + j) * 36 + qr] =
            make_float4(gv[0][j], gv[1][j], gv[2][j], gv[3][j]);
    // stage v once: 1024 float2, 16 per thread, coalesced
    {
        const float* vsrc = g_dw + (size_t)(192 + head * 32) * HWP;
        for (int i = tid; i < 1024; i += 64) {
            int d = i >> 5, pr = i & 31;
            int r = pr >> 2, j = (pr & 3) * 2;
            float2 v = *(const float2*)&vsrc[(size_t)d * HWP + (r0 + r) * WW + cc0 + j];
            *(float2*)&s_v[d * 64 + r * 8 + j] = v;
        }
    }
    __syncthreads();

    // AV: out[c][n] = sum_d G[c][d] v[d][n]; v via broadcast-friendly LDS
    {
        const int cog = tid >> 3, pxg = tid & 7;
        const int co = cog * 4;
        ull av[4][4] = {};
        #pragma unroll 4
        for (int d = 0; d < 32; d++) {
            float4 g4 = *(const float4*)&s_g[d * 36 + co];
            ull gp[4] = {pack2(g4.x), pack2(g4.y), pack2(g4.z), pack2(g4.w)};
            const ull* vr = (const ull*)&s_v[d * 64 + pxg * 8];
            ull v0 = vr[0], v1 = vr[1], v2 = vr[2], v3 = vr[3];
            #pragma unroll
            for (int i = 0; i < 4; i++) {
                fma2(av[i][0], gp[i], v0);
                fma2(av[i][1], gp[i], v1);
                fma2(av[i][2], gp[i], v2);
                fma2(av[i][3], gp[i], v3);
            }
        }
        float* base = g_out + (t * 96 + head * 32 + co) * 4096
                    + (wy * 8 + pxg) * 64 + wx * 8;
        #pragma unroll
        for (int i = 0; i < 4; i++) {
            *(float4*)(base + i * 4096)     = cat2(av[i][0], av[i][1]);
            *(float4*)(base + i * 4096 + 4) = cat2(av[i][2], av[i][3]);
        }
    }
}

// --------------------------------------------------------------------------
// K4: out = proj_w @ (gathered tile avg), f32x2, (+4,+4) unshift on store.
// --------------------------------------------------------------------------
__global__ __launch_bounds__(192) void proj_gemm_kernel(float* __restrict__ out)
{
    __shared__ float sWT[C * C];
    __shared__ float sX[KC * 128];
    __shared__ int   s_toff[128 * 4];
    __shared__ int   s_dst[128];
    __shared__ float s_icnt[128];

    const int tid = threadIdx.x;
    const int p0  = blockIdx.x * 128;

    if (tid < 128) {
        int p = p0 + tid; if (p >= HWP) p = HWP - 1;
        int h = p / WW, ww = p % WW;
        int hd = h + SHIFT; if (hd >= HH) hd -= HH;
        int wd = ww + SHIFT; if (wd >= WW) wd -= WW;
        s_dst[tid] = hd * WW + wd;
        int rt[2], ct[2], nr = 0, nc = 0;
        #pragma unroll
        for (int o = 0; o < 5; o++) {
            int off = c_off[o];
            if (off <= h  && h  < off + 64) rt[nr++] = o;
            if (off <= ww && ww < off + 64) ct[nc++] = o;
        }
        #pragma unroll
        for (int m = 0; m < 4; m++) s_toff[tid * 4 + m] = -1;
        int m = 0;
        for (int a = 0; a < nr; a++)
            for (int b = 0; b < nc; b++) {
                int tt = rt[a] * 5 + ct[b];
                s_toff[tid * 4 + m++] = tt * (96 * 4096)
                    + (h - c_off[rt[a]]) * 64 + (ww - c_off[ct[b]]);
            }
        s_icnt[tid] = 1.0f / (float)(nr * nc);
    }
    for (int i = tid; i < C * C; i += 192) sWT[i] = g_pwT[i];

    const int og = tid / 16, pg = tid % 16;
    ull acc[8][4] = {};

    for (int kc = 0; kc < C / KC; kc++) {
        __syncthreads();
        for (int i = tid; i < KC * 128; i += 192) {
            int k = i >> 7, px = i & 127;
            int cch = (kc * KC + k) * 4096;
            float s = 0.f;
            #pragma unroll
            for (int m = 0; m < 4; m++) {
                int off = s_toff[px * 4 + m];
                if (off >= 0) s += g_out[off + cch];
            }
            sX[k * 128 + px] = s * s_icnt[px];
        }
        __syncthreads();
        #pragma unroll
        for (int k = 0; k < KC; k++) {
            float4 wa = *(const float4*)&sWT[(kc * KC + k) * C + og * 8];
            float4 wb = *(const float4*)&sWT[(kc * KC + k) * C + og * 8 + 4];
            ull wp[8];
            wp[0] = pack2(wa.x); wp[1] = pack2(wa.y);
            wp[2] = pack2(wa.z); wp[3] = pack2(wa.w);
            wp[4] = pack2(wb.x); wp[5] = pack2(wb.y);
            wp[6] = pack2(wb.z); wp[7] = pack2(wb.w);
            ulonglong2 xa = *(const ulonglong2*)&sX[k * 128 + pg * 8];
            ulonglong2 xb = *(const ulonglong2*)&sX[k * 128 + pg * 8 + 4];
            #pragma unroll
            for (int o = 0; o < 8; o++) {
                fma2(acc[o][0], wp[o], xa.x);
                fma2(acc[o][1], wp[o], xa.y);
                fma2(acc[o][2], wp[o], xb.x);
                fma2(acc[o][3], wp[o], xb.y);
            }
        }
    }
    if (p0 + pg * 8 < HWP) {
        #pragma unroll
        for (int o = 0; o < 8; o++) {
            const int oc = og * 8 + o;
            float4 v0 = cat2(acc[o][0], acc[o][1]);
            float4 v1 = cat2(acc[o][2], acc[o][3]);
            float vv[8] = {v0.x, v0.y, v0.z, v0.w, v1.x, v1.y, v1.z, v1.w};
            #pragma unroll
            for (int j = 0; j < 8; j++)
                out[oc * HWP + s_dst[pg * 8 + j]] = vv[j];
        }
    }
}

// --------------------------------------------------------------------------
extern "C" void kernel_launch(void* const* d_in, const int* in_sizes, int n_in,
                              void* d_out, int out_size)
{
    const float* x    = (const float*)d_in[0];   // (1,96,264,264)
    const float* temp = (const float*)d_in[1];   // (3,1,1)
    const float* qkvw = (const float*)d_in[2];   // (288,96)
    const float* dww  = (const float*)d_in[3];   // (288,1,3,3)
    const float* pw   = (const float*)d_in[4];   // (96,96)
    float* out = (float*)d_out;                  // (1,96,264,264)

    transpose_w_kernel<<<(C3 * C + 255) / 256, 256>>>(qkvw, pw);
    qkv_gemm_kernel<<<dim3((HWP + 127) / 128, 3), 192>>>(x);
    dwconv_kernel<<<dim3((HWP / 8 + 255) / 256, C3), 256>>>(dww);
    attn_kernel<<<dim3(1600, 3), 64>>>(temp);
    proj_gemm_kernel<<<(HWP + 127) / 128, 192>>>(out);
}